// round 12
// baseline (speedup 1.0000x reference)
#include <cuda_runtime.h>
#include <cuda_fp16.h>

#define N_NODES 4096
#define FIN     128
#define NH      4
#define FOUT    64
#define HF      256
#define MAXD    256
#define NBLK    1536   // b%3 in {0,1} -> scan (1024 blocks), b%3==2 -> GEMM (512)

// -------- device scratch --------
__device__ float g_h[NH * N_NODES * FOUT];       // fp32 [h][n][f] (4 MB)
__device__ float g_ss[N_NODES * NH];             // src score [n][h]
__device__ float g_st[N_NODES * NH];             // tgt score [n][h] (float4-loadable)
__device__ float g_skip[N_NODES * HF];           // skip proj result
__device__ unsigned short g_adj[(size_t)N_NODES * MAXD];
__device__ int   g_deg[N_NODES];

static __device__ __forceinline__ unsigned pack_half2(float a, float b) {
    const __half2 h = __floats2half2_rn(a, b);
    return *(const unsigned*)&h;
}

// ============================================================
// Fat kernel (identical to R11 passing version).
// ============================================================
__global__ __launch_bounds__(128) void prep_kernel(
    const float* __restrict__ x,
    const float* __restrict__ mask,
    const float* __restrict__ proj,
    const float* __restrict__ score_src,
    const float* __restrict__ score_tgt,
    const float* __restrict__ skip_w)
{
    __shared__ uint4 xs4[64 * 16];   // A tile: 64 rows x 128 halves, swizzled (16 KB)
    __shared__ uint4 ws4[128 * 8];   // B tile: 16 KB
    __shared__ float redS[2][64], redT[2][64];

    const int b   = blockIdx.x;
    const int tid = threadIdx.x;

    if (b % 3 != 2) {
        // ---------------- scan role: warp per row ----------------
        const int sb   = (b / 3) * 2 + (b % 3);    // 0..1023
        const int wid  = tid >> 5;
        const int lane = tid & 31;
        const int row  = sb * 4 + wid;
        const float4* mr = (const float4*)(mask + (size_t)row * N_NODES);
        unsigned short* adj = g_adj + (size_t)row * MAXD;
        const unsigned lt = (1u << lane) - 1u;
        int base = 0;
#pragma unroll 16
        for (int g = 0; g < N_NODES / 128; g++) {
            const float4 v = mr[g * 32 + lane];
            const unsigned b0 = __ballot_sync(0xffffffffu, v.x == 0.f);
            const unsigned b1 = __ballot_sync(0xffffffffu, v.y == 0.f);
            const unsigned b2 = __ballot_sync(0xffffffffu, v.z == 0.f);
            const unsigned b3 = __ballot_sync(0xffffffffu, v.w == 0.f);
            const int c0 = __popc(b0), c1 = __popc(b1), c2 = __popc(b2), c3 = __popc(b3);
            const int e0 = g * 128 + lane * 4;
            if (v.x == 0.f) { int p = base + __popc(b0 & lt);                if (p < MAXD) adj[p] = (unsigned short)(e0);     }
            if (v.y == 0.f) { int p = base + c0 + __popc(b1 & lt);           if (p < MAXD) adj[p] = (unsigned short)(e0 + 1); }
            if (v.z == 0.f) { int p = base + c0 + c1 + __popc(b2 & lt);      if (p < MAXD) adj[p] = (unsigned short)(e0 + 2); }
            if (v.w == 0.f) { int p = base + c0 + c1 + c2 + __popc(b3 & lt); if (p < MAXD) adj[p] = (unsigned short)(e0 + 3); }
            base += c0 + c1 + c2 + c3;
        }
        if (lane == 0) g_deg[row] = min(base, MAXD);
        return;
    }

    // ---------------- GEMM role ----------------
    const int gb = b / 3;            // 0..511
    const int rt = gb >> 3;          // row tile 0..63
    const int ct = gb & 7;           // col tile 0..7
    const int r0 = rt * 64;
    const int w    = tid >> 5;       // warp 0..3
    const int lane = tid & 31;
    const int wr = (w >> 1) * 32;
    const int wc = (w & 1) * 32;

    // ---- stage A ----
    {
        const float4* xg = (const float4*)(x + (size_t)r0 * FIN);
#pragma unroll
        for (int i = 0; i < 8; i++) {
            const int idx = tid + i * 128;
            const int r = idx >> 4, c8 = idx & 15;
            const float4 v0 = xg[r * 32 + c8 * 2];
            const float4 v1 = xg[r * 32 + c8 * 2 + 1];
            uint4 pk;
            pk.x = pack_half2(v0.x, v0.y);
            pk.y = pack_half2(v0.z, v0.w);
            pk.z = pack_half2(v1.x, v1.y);
            pk.w = pack_half2(v1.z, v1.w);
            xs4[r * 16 + (c8 ^ (r & 7))] = pk;
        }
    }
    // ---- stage B ----
    if (ct >= 4) {
        const float4* wg = (const float4*)(skip_w + (size_t)((ct - 4) * 64) * FIN);
#pragma unroll
        for (int i = 0; i < 8; i++) {
            const int idx = tid + i * 128;
            const int r = idx >> 4, c8 = idx & 15;
            const float4 v0 = wg[r * 32 + c8 * 2];
            const float4 v1 = wg[r * 32 + c8 * 2 + 1];
            uint4 pk;
            pk.x = pack_half2(v0.x, v0.y);
            pk.y = pack_half2(v0.z, v0.w);
            pk.z = pack_half2(v1.x, v1.y);
            pk.w = pack_half2(v1.z, v1.w);
            ws4[r * 16 + (c8 ^ (r & 7))] = pk;
        }
    } else {
        const float4* pg = (const float4*)(proj + (size_t)ct * FIN * FOUT);
#pragma unroll
        for (int i = 0; i < 8; i++) {
            const int idx = tid + i * 128;
            const int r = idx >> 3, c8 = idx & 7;
            const float4 v0 = pg[r * 16 + c8 * 2];
            const float4 v1 = pg[r * 16 + c8 * 2 + 1];
            uint4 pk;
            pk.x = pack_half2(v0.x, v0.y);
            pk.y = pack_half2(v0.z, v0.w);
            pk.z = pack_half2(v1.x, v1.y);
            pk.w = pack_half2(v1.z, v1.w);
            ws4[r * 8 + (c8 ^ (r & 7))] = pk;
        }
    }
    __syncthreads();

    // ---- mma compute ----
    float acc[2][4][4];
#pragma unroll
    for (int mi = 0; mi < 2; mi++)
#pragma unroll
        for (int ni = 0; ni < 4; ni++)
#pragma unroll
            for (int t = 0; t < 4; t++) acc[mi][ni][t] = 0.f;

    const unsigned xsb = (unsigned)__cvta_generic_to_shared(xs4);
    const unsigned wsb = (unsigned)__cvta_generic_to_shared(ws4);

#pragma unroll
    for (int kc = 0; kc < 8; kc++) {
        unsigned a[2][4];
#pragma unroll
        for (int mi = 0; mi < 2; mi++) {
            const int rl = wr + mi * 16 + (lane & 15);
            const int ch = kc * 2 + (lane >> 4);
            const unsigned ad = xsb + rl * 256 + ((ch ^ (rl & 7)) << 4);
            asm volatile("ldmatrix.sync.aligned.m8n8.x4.shared.b16 {%0,%1,%2,%3}, [%4];"
                         : "=r"(a[mi][0]), "=r"(a[mi][1]), "=r"(a[mi][2]), "=r"(a[mi][3])
                         : "r"(ad));
        }
        unsigned bf[4][2];
        if (ct >= 4) {
#pragma unroll
            for (int ni = 0; ni < 4; ni++) {
                const int cl = wc + ni * 8 + (lane & 7);
                const int ch = kc * 2 + ((lane >> 3) & 1);
                const unsigned ad = wsb + cl * 256 + ((ch ^ (cl & 7)) << 4);
                asm volatile("ldmatrix.sync.aligned.m8n8.x2.shared.b16 {%0,%1}, [%2];"
                             : "=r"(bf[ni][0]), "=r"(bf[ni][1])
                             : "r"(ad));
            }
        } else {
#pragma unroll
            for (int ni = 0; ni < 4; ni++) {
                const int k  = kc * 16 + (lane & 15);
                const int c8 = (wc >> 3) + ni;
                const unsigned ad = wsb + (k * 8 + (c8 ^ (k & 7))) * 16;
                asm volatile("ldmatrix.sync.aligned.m8n8.x2.trans.shared.b16 {%0,%1}, [%2];"
                             : "=r"(bf[ni][0]), "=r"(bf[ni][1])
                             : "r"(ad));
            }
        }
#pragma unroll
        for (int mi = 0; mi < 2; mi++)
#pragma unroll
            for (int ni = 0; ni < 4; ni++)
                asm volatile("mma.sync.aligned.m16n8k16.row.col.f32.f16.f16.f32 "
                             "{%0,%1,%2,%3}, {%4,%5,%6,%7}, {%8,%9}, {%0,%1,%2,%3};"
                             : "+f"(acc[mi][ni][0]), "+f"(acc[mi][ni][1]),
                               "+f"(acc[mi][ni][2]), "+f"(acc[mi][ni][3])
                             : "r"(a[mi][0]), "r"(a[mi][1]), "r"(a[mi][2]), "r"(a[mi][3]),
                               "r"(bf[ni][0]), "r"(bf[ni][1]));
    }

    // ---- epilogue ----
    const int g   = lane >> 2;
    const int tig = lane & 3;
    if (ct < 4) {
        const int h = ct;
#pragma unroll
        for (int mi = 0; mi < 2; mi++) {
            const int lr1 = wr + mi * 16 + g;
            const int lr2 = lr1 + 8;
            float sS1 = 0.f, sT1 = 0.f, sS2 = 0.f, sT2 = 0.f;
#pragma unroll
            for (int ni = 0; ni < 4; ni++) {
                const int c0c = wc + ni * 8 + tig * 2;
                const float sv0 = score_src[h * FOUT + c0c];
                const float sv1 = score_src[h * FOUT + c0c + 1];
                const float tv0 = score_tgt[h * FOUT + c0c];
                const float tv1 = score_tgt[h * FOUT + c0c + 1];
                const float2 hi = {acc[mi][ni][0], acc[mi][ni][1]};
                const float2 lo = {acc[mi][ni][2], acc[mi][ni][3]};
                *(float2*)(g_h + ((size_t)h * N_NODES + r0 + lr1) * FOUT + c0c) = hi;
                *(float2*)(g_h + ((size_t)h * N_NODES + r0 + lr2) * FOUT + c0c) = lo;
                sS1 += hi.x * sv0 + hi.y * sv1;  sT1 += hi.x * tv0 + hi.y * tv1;
                sS2 += lo.x * sv0 + lo.y * sv1;  sT2 += lo.x * tv0 + lo.y * tv1;
            }
#pragma unroll
            for (int o = 1; o < 4; o <<= 1) {
                sS1 += __shfl_xor_sync(0xffffffffu, sS1, o);
                sT1 += __shfl_xor_sync(0xffffffffu, sT1, o);
                sS2 += __shfl_xor_sync(0xffffffffu, sS2, o);
                sT2 += __shfl_xor_sync(0xffffffffu, sT2, o);
            }
            if (tig == 0) {
                redS[w & 1][lr1] = sS1;  redT[w & 1][lr1] = sT1;
                redS[w & 1][lr2] = sS2;  redT[w & 1][lr2] = sT2;
            }
        }
        __syncthreads();
        if (tid < 64) {
            g_ss[(r0 + tid) * NH + h] = redS[0][tid] + redS[1][tid];
            g_st[(r0 + tid) * NH + h] = redT[0][tid] + redT[1][tid];
        }
    } else {
        const int c0g = (ct - 4) * 64;
#pragma unroll
        for (int mi = 0; mi < 2; mi++) {
            const int lr1 = wr + mi * 16 + g;
            const int lr2 = lr1 + 8;
#pragma unroll
            for (int ni = 0; ni < 4; ni++) {
                const int cc = c0g + wc + ni * 8 + tig * 2;
                const float2 hi = {acc[mi][ni][0], acc[mi][ni][1]};
                const float2 lo = {acc[mi][ni][2], acc[mi][ni][3]};
                *(float2*)(g_skip + (size_t)(r0 + lr1) * HF + cc) = hi;
                *(float2*)(g_skip + (size_t)(r0 + lr2) * HF + cc) = lo;
            }
        }
    }
}

// ============================================================
// Attention kernel (R7/R10 structure), occupancy-forced:
// __launch_bounds__(128, 16) -> 32 regs/thread, ~2048 thr/SM.
// ============================================================
__global__ __launch_bounds__(128, 16) void attn_kernel(
    const float* __restrict__ bias,
    float* __restrict__ out)
{
    const int n    = blockIdx.x;
    const int tid  = threadIdx.x;
    const int h    = tid >> 5;
    const int lane = tid & 31;

    __shared__ float2 pair[NH][MAXD];
    __shared__ float  partS[NH][NH + 1];

    const int deg = g_deg[n];
    const float4 ss4 = *(const float4*)(g_ss + (size_t)n * NH);
    const float4* st4 = (const float4*)g_st;
    const unsigned short* adj = g_adj + (size_t)n * MAXD;

    float s0 = 0.f, s1 = 0.f, s2 = 0.f, s3 = 0.f;
    for (int j = tid; j < deg; j += 128) {
        const int m = adj[j];
        const float4 st = st4[m];
        float v0 = ss4.x + st.x; v0 = v0 > 0.f ? v0 : 0.2f * v0;
        float v1 = ss4.y + st.y; v1 = v1 > 0.f ? v1 : 0.2f * v1;
        float v2 = ss4.z + st.z; v2 = v2 > 0.f ? v2 : 0.2f * v2;
        float v3 = ss4.w + st.w; v3 = v3 > 0.f ? v3 : 0.2f * v3;
        const float e0 = __expf(v0), e1 = __expf(v1);
        const float e2 = __expf(v2), e3 = __expf(v3);
        const float fo = __int_as_float(m * FOUT);
        pair[0][j] = make_float2(e0, fo);
        pair[1][j] = make_float2(e1, fo);
        pair[2][j] = make_float2(e2, fo);
        pair[3][j] = make_float2(e3, fo);
        s0 += e0; s1 += e1; s2 += e2; s3 += e3;
    }
#pragma unroll
    for (int o = 16; o; o >>= 1) {
        s0 += __shfl_xor_sync(0xffffffffu, s0, o);
        s1 += __shfl_xor_sync(0xffffffffu, s1, o);
        s2 += __shfl_xor_sync(0xffffffffu, s2, o);
        s3 += __shfl_xor_sync(0xffffffffu, s3, o);
    }
    if (lane == 0) {
        partS[h][0] = s0; partS[h][1] = s1;
        partS[h][2] = s2; partS[h][3] = s3;
    }
    __syncthreads();
    const float S = partS[0][h] + partS[1][h] + partS[2][h] + partS[3][h];

    const int g = lane >> 4;
    const int q = lane & 15;
    const float* hb = g_h + ((size_t)h * N_NODES) * FOUT + q * 4;
    float4 aA = {0.f, 0.f, 0.f, 0.f};
    float4 aB = {0.f, 0.f, 0.f, 0.f};
    int j = g;
    for (; j + 6 < deg; j += 8) {
        const float2 p0 = pair[h][j];
        const float2 p1 = pair[h][j + 2];
        const float2 p2 = pair[h][j + 4];
        const float2 p3 = pair[h][j + 6];
        const float4 v0 = *(const float4*)(hb + __float_as_int(p0.y));
        const float4 v1 = *(const float4*)(hb + __float_as_int(p1.y));
        const float4 v2 = *(const float4*)(hb + __float_as_int(p2.y));
        const float4 v3 = *(const float4*)(hb + __float_as_int(p3.y));
        aA.x = fmaf(p0.x, v0.x, aA.x); aA.y = fmaf(p0.x, v0.y, aA.y);
        aA.z = fmaf(p0.x, v0.z, aA.z); aA.w = fmaf(p0.x, v0.w, aA.w);
        aB.x = fmaf(p1.x, v1.x, aB.x); aB.y = fmaf(p1.x, v1.y, aB.y);
        aB.z = fmaf(p1.x, v1.z, aB.z); aB.w = fmaf(p1.x, v1.w, aB.w);
        aA.x = fmaf(p2.x, v2.x, aA.x); aA.y = fmaf(p2.x, v2.y, aA.y);
        aA.z = fmaf(p2.x, v2.z, aA.z); aA.w = fmaf(p2.x, v2.w, aA.w);
        aB.x = fmaf(p3.x, v3.x, aB.x); aB.y = fmaf(p3.x, v3.y, aB.y);
        aB.z = fmaf(p3.x, v3.z, aB.z); aB.w = fmaf(p3.x, v3.w, aB.w);
    }
    for (; j < deg; j += 2) {
        const float2 pr = pair[h][j];
        const float4 v  = *(const float4*)(hb + __float_as_int(pr.y));
        aA.x = fmaf(pr.x, v.x, aA.x); aA.y = fmaf(pr.x, v.y, aA.y);
        aA.z = fmaf(pr.x, v.z, aA.z); aA.w = fmaf(pr.x, v.w, aA.w);
    }
    float4 a = {aA.x + aB.x, aA.y + aB.y, aA.z + aB.z, aA.w + aB.w};
    a.x += __shfl_xor_sync(0xffffffffu, a.x, 16);
    a.y += __shfl_xor_sync(0xffffffffu, a.y, 16);
    a.z += __shfl_xor_sync(0xffffffffu, a.z, 16);
    a.w += __shfl_xor_sync(0xffffffffu, a.w, 16);

    if (g == 0) {
        const float inv = 1.f / S;
        const int c4 = h * 16 + q;
        const float4 sk = ((const float4*)(g_skip + (size_t)n * HF))[c4];
        const float4 bi = ((const float4*)bias)[c4];
        float o0 = a.x * inv + sk.x + bi.x;
        float o1 = a.y * inv + sk.y + bi.y;
        float o2 = a.z * inv + sk.z + bi.z;
        float o3 = a.w * inv + sk.w + bi.w;
        o0 = o0 > 0.f ? o0 : (__expf(o0) - 1.f);
        o1 = o1 > 0.f ? o1 : (__expf(o1) - 1.f);
        o2 = o2 > 0.f ? o2 : (__expf(o2) - 1.f);
        o3 = o3 > 0.f ? o3 : (__expf(o3) - 1.f);
        const float4 res = {o0, o1, o2, o3};
        ((float4*)(out + (size_t)n * HF))[c4] = res;
    }
}

// ============================================================
extern "C" void kernel_launch(void* const* d_in, const int* in_sizes, int n_in,
                              void* d_out, int out_size)
{
    const float* x         = (const float*)d_in[0];
    const float* mask      = (const float*)d_in[1];
    const float* proj      = (const float*)d_in[2];
    const float* score_src = (const float*)d_in[3];
    const float* score_tgt = (const float*)d_in[4];
    const float* skip_w    = (const float*)d_in[5];
    const float* bias      = (const float*)d_in[6];
    float* out             = (float*)d_out;

    prep_kernel<<<NBLK, 128>>>(x, mask, proj, score_src, score_tgt, skip_w);
    attn_kernel<<<N_NODES, 128>>>(bias, out);
}

// round 13
// speedup vs baseline: 1.1941x; 1.1941x over previous
#include <cuda_runtime.h>
#include <cuda_fp16.h>

#define N_NODES 4096
#define FIN     128
#define NH      4
#define FOUT    64
#define HF      256
#define MAXD    256
#define NBLK    1536   // b%3 in {0,1} -> scan (1024 blocks), b%3==2 -> GEMM (512)

// -------- device scratch --------
__device__ __half g_h2[NH * N_NODES * FOUT];     // fp16 [h][n][f] (2 MB), 128B/row
__device__ float  g_ss[N_NODES * NH];            // src score [n][h]
__device__ float  g_st[N_NODES * NH];            // tgt score [n][h] (float4-loadable)
__device__ float  g_skip[N_NODES * HF];          // skip proj result
__device__ unsigned short g_adj[(size_t)N_NODES * MAXD];
__device__ int    g_deg[N_NODES];

static __device__ __forceinline__ unsigned pack_half2(float a, float b) {
    const __half2 h = __floats2half2_rn(a, b);
    return *(const unsigned*)&h;
}

// ============================================================
// Fat kernel (R11-proven GEMM/scan; epilogue stores g_h2 fp16).
// ============================================================
__global__ __launch_bounds__(128) void prep_kernel(
    const float* __restrict__ x,
    const float* __restrict__ mask,
    const float* __restrict__ proj,
    const float* __restrict__ score_src,
    const float* __restrict__ score_tgt,
    const float* __restrict__ skip_w)
{
    __shared__ uint4 xs4[64 * 16];   // A tile (16 KB)
    __shared__ uint4 ws4[128 * 8];   // B tile (16 KB)
    __shared__ float redS[2][64], redT[2][64];

    const int b   = blockIdx.x;
    const int tid = threadIdx.x;

    if (b % 3 != 2) {
        // ---------------- scan role: warp per row ----------------
        const int sb   = (b / 3) * 2 + (b % 3);    // 0..1023
        const int wid  = tid >> 5;
        const int lane = tid & 31;
        const int row  = sb * 4 + wid;
        const float4* mr = (const float4*)(mask + (size_t)row * N_NODES);
        unsigned short* adj = g_adj + (size_t)row * MAXD;
        const unsigned lt = (1u << lane) - 1u;
        int base = 0;
#pragma unroll 16
        for (int g = 0; g < N_NODES / 128; g++) {
            const float4 v = mr[g * 32 + lane];
            const unsigned b0 = __ballot_sync(0xffffffffu, v.x == 0.f);
            const unsigned b1 = __ballot_sync(0xffffffffu, v.y == 0.f);
            const unsigned b2 = __ballot_sync(0xffffffffu, v.z == 0.f);
            const unsigned b3 = __ballot_sync(0xffffffffu, v.w == 0.f);
            const int c0 = __popc(b0), c1 = __popc(b1), c2 = __popc(b2), c3 = __popc(b3);
            const int e0 = g * 128 + lane * 4;
            if (v.x == 0.f) { int p = base + __popc(b0 & lt);                if (p < MAXD) adj[p] = (unsigned short)(e0);     }
            if (v.y == 0.f) { int p = base + c0 + __popc(b1 & lt);           if (p < MAXD) adj[p] = (unsigned short)(e0 + 1); }
            if (v.z == 0.f) { int p = base + c0 + c1 + __popc(b2 & lt);      if (p < MAXD) adj[p] = (unsigned short)(e0 + 2); }
            if (v.w == 0.f) { int p = base + c0 + c1 + c2 + __popc(b3 & lt); if (p < MAXD) adj[p] = (unsigned short)(e0 + 3); }
            base += c0 + c1 + c2 + c3;
        }
        if (lane == 0) g_deg[row] = min(base, MAXD);
        return;
    }

    // ---------------- GEMM role ----------------
    const int gb = b / 3;            // 0..511
    const int rt = gb >> 3;          // row tile 0..63
    const int ct = gb & 7;           // col tile 0..7
    const int r0 = rt * 64;
    const int w    = tid >> 5;       // warp 0..3
    const int lane = tid & 31;
    const int wr = (w >> 1) * 32;
    const int wc = (w & 1) * 32;

    // ---- stage A ----
    {
        const float4* xg = (const float4*)(x + (size_t)r0 * FIN);
#pragma unroll
        for (int i = 0; i < 8; i++) {
            const int idx = tid + i * 128;
            const int r = idx >> 4, c8 = idx & 15;
            const float4 v0 = xg[r * 32 + c8 * 2];
            const float4 v1 = xg[r * 32 + c8 * 2 + 1];
            uint4 pk;
            pk.x = pack_half2(v0.x, v0.y);
            pk.y = pack_half2(v0.z, v0.w);
            pk.z = pack_half2(v1.x, v1.y);
            pk.w = pack_half2(v1.z, v1.w);
            xs4[r * 16 + (c8 ^ (r & 7))] = pk;
        }
    }
    // ---- stage B ----
    if (ct >= 4) {
        const float4* wg = (const float4*)(skip_w + (size_t)((ct - 4) * 64) * FIN);
#pragma unroll
        for (int i = 0; i < 8; i++) {
            const int idx = tid + i * 128;
            const int r = idx >> 4, c8 = idx & 15;
            const float4 v0 = wg[r * 32 + c8 * 2];
            const float4 v1 = wg[r * 32 + c8 * 2 + 1];
            uint4 pk;
            pk.x = pack_half2(v0.x, v0.y);
            pk.y = pack_half2(v0.z, v0.w);
            pk.z = pack_half2(v1.x, v1.y);
            pk.w = pack_half2(v1.z, v1.w);
            ws4[r * 16 + (c8 ^ (r & 7))] = pk;
        }
    } else {
        const float4* pg = (const float4*)(proj + (size_t)ct * FIN * FOUT);
#pragma unroll
        for (int i = 0; i < 8; i++) {
            const int idx = tid + i * 128;
            const int r = idx >> 3, c8 = idx & 7;
            const float4 v0 = pg[r * 16 + c8 * 2];
            const float4 v1 = pg[r * 16 + c8 * 2 + 1];
            uint4 pk;
            pk.x = pack_half2(v0.x, v0.y);
            pk.y = pack_half2(v0.z, v0.w);
            pk.z = pack_half2(v1.x, v1.y);
            pk.w = pack_half2(v1.z, v1.w);
            ws4[r * 8 + (c8 ^ (r & 7))] = pk;
        }
    }
    __syncthreads();

    // ---- mma compute ----
    float acc[2][4][4];
#pragma unroll
    for (int mi = 0; mi < 2; mi++)
#pragma unroll
        for (int ni = 0; ni < 4; ni++)
#pragma unroll
            for (int t = 0; t < 4; t++) acc[mi][ni][t] = 0.f;

    const unsigned xsb = (unsigned)__cvta_generic_to_shared(xs4);
    const unsigned wsb = (unsigned)__cvta_generic_to_shared(ws4);

#pragma unroll
    for (int kc = 0; kc < 8; kc++) {
        unsigned a[2][4];
#pragma unroll
        for (int mi = 0; mi < 2; mi++) {
            const int rl = wr + mi * 16 + (lane & 15);
            const int ch = kc * 2 + (lane >> 4);
            const unsigned ad = xsb + rl * 256 + ((ch ^ (rl & 7)) << 4);
            asm volatile("ldmatrix.sync.aligned.m8n8.x4.shared.b16 {%0,%1,%2,%3}, [%4];"
                         : "=r"(a[mi][0]), "=r"(a[mi][1]), "=r"(a[mi][2]), "=r"(a[mi][3])
                         : "r"(ad));
        }
        unsigned bf[4][2];
        if (ct >= 4) {
#pragma unroll
            for (int ni = 0; ni < 4; ni++) {
                const int cl = wc + ni * 8 + (lane & 7);
                const int ch = kc * 2 + ((lane >> 3) & 1);
                const unsigned ad = wsb + cl * 256 + ((ch ^ (cl & 7)) << 4);
                asm volatile("ldmatrix.sync.aligned.m8n8.x2.shared.b16 {%0,%1}, [%2];"
                             : "=r"(bf[ni][0]), "=r"(bf[ni][1])
                             : "r"(ad));
            }
        } else {
#pragma unroll
            for (int ni = 0; ni < 4; ni++) {
                const int k  = kc * 16 + (lane & 15);
                const int c8 = (wc >> 3) + ni;
                const unsigned ad = wsb + (k * 8 + (c8 ^ (k & 7))) * 16;
                asm volatile("ldmatrix.sync.aligned.m8n8.x2.trans.shared.b16 {%0,%1}, [%2];"
                             : "=r"(bf[ni][0]), "=r"(bf[ni][1])
                             : "r"(ad));
            }
        }
#pragma unroll
        for (int mi = 0; mi < 2; mi++)
#pragma unroll
            for (int ni = 0; ni < 4; ni++)
                asm volatile("mma.sync.aligned.m16n8k16.row.col.f32.f16.f16.f32 "
                             "{%0,%1,%2,%3}, {%4,%5,%6,%7}, {%8,%9}, {%0,%1,%2,%3};"
                             : "+f"(acc[mi][ni][0]), "+f"(acc[mi][ni][1]),
                               "+f"(acc[mi][ni][2]), "+f"(acc[mi][ni][3])
                             : "r"(a[mi][0]), "r"(a[mi][1]), "r"(a[mi][2]), "r"(a[mi][3]),
                               "r"(bf[ni][0]), "r"(bf[ni][1]));
    }

    // ---- epilogue ----
    const int g   = lane >> 2;
    const int tig = lane & 3;
    if (ct < 4) {
        const int h = ct;
#pragma unroll
        for (int mi = 0; mi < 2; mi++) {
            const int lr1 = wr + mi * 16 + g;
            const int lr2 = lr1 + 8;
            float sS1 = 0.f, sT1 = 0.f, sS2 = 0.f, sT2 = 0.f;
#pragma unroll
            for (int ni = 0; ni < 4; ni++) {
                const int c0c = wc + ni * 8 + tig * 2;
                const float sv0 = score_src[h * FOUT + c0c];
                const float sv1 = score_src[h * FOUT + c0c + 1];
                const float tv0 = score_tgt[h * FOUT + c0c];
                const float tv1 = score_tgt[h * FOUT + c0c + 1];
                const float2 hi = {acc[mi][ni][0], acc[mi][ni][1]};
                const float2 lo = {acc[mi][ni][2], acc[mi][ni][3]};
                *(unsigned*)((char*)g_h2 + (((size_t)h * N_NODES + r0 + lr1) * FOUT + c0c) * 2) = pack_half2(hi.x, hi.y);
                *(unsigned*)((char*)g_h2 + (((size_t)h * N_NODES + r0 + lr2) * FOUT + c0c) * 2) = pack_half2(lo.x, lo.y);
                sS1 += hi.x * sv0 + hi.y * sv1;  sT1 += hi.x * tv0 + hi.y * tv1;
                sS2 += lo.x * sv0 + lo.y * sv1;  sT2 += lo.x * tv0 + lo.y * tv1;
            }
#pragma unroll
            for (int o = 1; o < 4; o <<= 1) {
                sS1 += __shfl_xor_sync(0xffffffffu, sS1, o);
                sT1 += __shfl_xor_sync(0xffffffffu, sT1, o);
                sS2 += __shfl_xor_sync(0xffffffffu, sS2, o);
                sT2 += __shfl_xor_sync(0xffffffffu, sT2, o);
            }
            if (tig == 0) {
                redS[w & 1][lr1] = sS1;  redT[w & 1][lr1] = sT1;
                redS[w & 1][lr2] = sS2;  redT[w & 1][lr2] = sT2;
            }
        }
        __syncthreads();
        if (tid < 64) {
            g_ss[(r0 + tid) * NH + h] = redS[0][tid] + redS[1][tid];
            g_st[(r0 + tid) * NH + h] = redT[0][tid] + redT[1][tid];
        }
    } else {
        const int c0g = (ct - 4) * 64;
#pragma unroll
        for (int mi = 0; mi < 2; mi++) {
            const int lr1 = wr + mi * 16 + g;
            const int lr2 = lr1 + 8;
#pragma unroll
            for (int ni = 0; ni < 4; ni++) {
                const int cc = c0g + wc + ni * 8 + tig * 2;
                const float2 hi = {acc[mi][ni][0], acc[mi][ni][1]};
                const float2 lo = {acc[mi][ni][2], acc[mi][ni][3]};
                *(float2*)(g_skip + (size_t)(r0 + lr1) * HF + cc) = hi;
                *(float2*)(g_skip + (size_t)(r0 + lr2) * HF + cc) = lo;
            }
        }
    }
}

// ============================================================
// Attention kernel (R10 structure, fp16 h gathers).
// 16-lane subgroup covers one 128B neighbor row via uint2 loads.
// Lane q owns feats 4q..4q+3 (same output mapping as fp32 ver).
// ============================================================
__global__ __launch_bounds__(128) void attn_kernel(
    const float* __restrict__ bias,
    float* __restrict__ out)
{
    const int n    = blockIdx.x;
    const int tid  = threadIdx.x;
    const int h    = tid >> 5;
    const int lane = tid & 31;

    __shared__ float2 pair[NH][MAXD];    // {exp(v), float-as-int(m*128 byte offset)}
    __shared__ float  partS[NH][NH + 1];

    const int deg = g_deg[n];
    const float4 ss4 = *(const float4*)(g_ss + (size_t)n * NH);
    const float4* st4 = (const float4*)g_st;
    const unsigned short* adj = g_adj + (size_t)n * MAXD;

    float s0 = 0.f, s1 = 0.f, s2 = 0.f, s3 = 0.f;
    for (int j = tid; j < deg; j += 128) {
        const int m = adj[j];
        const float4 st = st4[m];
        float v0 = ss4.x + st.x; v0 = v0 > 0.f ? v0 : 0.2f * v0;
        float v1 = ss4.y + st.y; v1 = v1 > 0.f ? v1 : 0.2f * v1;
        float v2 = ss4.z + st.z; v2 = v2 > 0.f ? v2 : 0.2f * v2;
        float v3 = ss4.w + st.w; v3 = v3 > 0.f ? v3 : 0.2f * v3;
        const float e0 = __expf(v0), e1 = __expf(v1);
        const float e2 = __expf(v2), e3 = __expf(v3);
        const float fo = __int_as_float(m * (FOUT * 2));   // byte offset of fp16 row
        pair[0][j] = make_float2(e0, fo);
        pair[1][j] = make_float2(e1, fo);
        pair[2][j] = make_float2(e2, fo);
        pair[3][j] = make_float2(e3, fo);
        s0 += e0; s1 += e1; s2 += e2; s3 += e3;
    }
#pragma unroll
    for (int o = 16; o; o >>= 1) {
        s0 += __shfl_xor_sync(0xffffffffu, s0, o);
        s1 += __shfl_xor_sync(0xffffffffu, s1, o);
        s2 += __shfl_xor_sync(0xffffffffu, s2, o);
        s3 += __shfl_xor_sync(0xffffffffu, s3, o);
    }
    if (lane == 0) {
        partS[h][0] = s0; partS[h][1] = s1;
        partS[h][2] = s2; partS[h][3] = s3;
    }
    __syncthreads();
    const float S = partS[0][h] + partS[1][h] + partS[2][h] + partS[3][h];

    // gather: subgroup g of 16 lanes handles j = g, g+2, ...; lane q -> 8 bytes (4 halves)
    const int g = lane >> 4;
    const int q = lane & 15;
    const char* hb = (const char*)g_h2 + (size_t)h * N_NODES * (FOUT * 2) + q * 8;
    float4 aA = {0.f, 0.f, 0.f, 0.f};
    float4 aB = {0.f, 0.f, 0.f, 0.f};
    int j = g;
    for (; j + 6 < deg; j += 8) {
        const float2 p0 = pair[h][j];
        const float2 p1 = pair[h][j + 2];
        const float2 p2 = pair[h][j + 4];
        const float2 p3 = pair[h][j + 6];
        const uint2 h0 = *(const uint2*)(hb + __float_as_int(p0.y));
        const uint2 h1 = *(const uint2*)(hb + __float_as_int(p1.y));
        const uint2 h2 = *(const uint2*)(hb + __float_as_int(p2.y));
        const uint2 h3 = *(const uint2*)(hb + __float_as_int(p3.y));
        const float2 f00 = __half22float2(*(const __half2*)&h0.x);
        const float2 f01 = __half22float2(*(const __half2*)&h0.y);
        const float2 f10 = __half22float2(*(const __half2*)&h1.x);
        const float2 f11 = __half22float2(*(const __half2*)&h1.y);
        const float2 f20 = __half22float2(*(const __half2*)&h2.x);
        const float2 f21 = __half22float2(*(const __half2*)&h2.y);
        const float2 f30 = __half22float2(*(const __half2*)&h3.x);
        const float2 f31 = __half22float2(*(const __half2*)&h3.y);
        aA.x = fmaf(p0.x, f00.x, aA.x); aA.y = fmaf(p0.x, f00.y, aA.y);
        aA.z = fmaf(p0.x, f01.x, aA.z); aA.w = fmaf(p0.x, f01.y, aA.w);
        aB.x = fmaf(p1.x, f10.x, aB.x); aB.y = fmaf(p1.x, f10.y, aB.y);
        aB.z = fmaf(p1.x, f11.x, aB.z); aB.w = fmaf(p1.x, f11.y, aB.w);
        aA.x = fmaf(p2.x, f20.x, aA.x); aA.y = fmaf(p2.x, f20.y, aA.y);
        aA.z = fmaf(p2.x, f21.x, aA.z); aA.w = fmaf(p2.x, f21.y, aA.w);
        aB.x = fmaf(p3.x, f30.x, aB.x); aB.y = fmaf(p3.x, f30.y, aB.y);
        aB.z = fmaf(p3.x, f31.x, aB.z); aB.w = fmaf(p3.x, f31.y, aB.w);
    }
    for (; j < deg; j += 2) {
        const float2 pr = pair[h][j];
        const uint2 hv = *(const uint2*)(hb + __float_as_int(pr.y));
        const float2 f0 = __half22float2(*(const __half2*)&hv.x);
        const float2 f1 = __half22float2(*(const __half2*)&hv.y);
        aA.x = fmaf(pr.x, f0.x, aA.x); aA.y = fmaf(pr.x, f0.y, aA.y);
        aA.z = fmaf(pr.x, f1.x, aA.z); aA.w = fmaf(pr.x, f1.y, aA.w);
    }
    float4 a = {aA.x + aB.x, aA.y + aB.y, aA.z + aB.z, aA.w + aB.w};
    a.x += __shfl_xor_sync(0xffffffffu, a.x, 16);
    a.y += __shfl_xor_sync(0xffffffffu, a.y, 16);
    a.z += __shfl_xor_sync(0xffffffffu, a.z, 16);
    a.w += __shfl_xor_sync(0xffffffffu, a.w, 16);

    if (g == 0) {
        const float inv = 1.f / S;
        const int c4 = h * 16 + q;
        const float4 sk = ((const float4*)(g_skip + (size_t)n * HF))[c4];
        const float4 bi = ((const float4*)bias)[c4];
        float o0 = a.x * inv + sk.x + bi.x;
        float o1 = a.y * inv + sk.y + bi.y;
        float o2 = a.z * inv + sk.z + bi.z;
        float o3 = a.w * inv + sk.w + bi.w;
        o0 = o0 > 0.f ? o0 : (__expf(o0) - 1.f);
        o1 = o1 > 0.f ? o1 : (__expf(o1) - 1.f);
        o2 = o2 > 0.f ? o2 : (__expf(o2) - 1.f);
        o3 = o3 > 0.f ? o3 : (__expf(o3) - 1.f);
        const float4 res = {o0, o1, o2, o3};
        ((float4*)(out + (size_t)n * HF))[c4] = res;
    }
}

// ============================================================
extern "C" void kernel_launch(void* const* d_in, const int* in_sizes, int n_in,
                              void* d_out, int out_size)
{
    const float* x         = (const float*)d_in[0];
    const float* mask      = (const float*)d_in[1];
    const float* proj      = (const float*)d_in[2];
    const float* score_src = (const float*)d_in[3];
    const float* score_tgt = (const float*)d_in[4];
    const float* skip_w    = (const float*)d_in[5];
    const float* bias      = (const float*)d_in[6];
    float* out             = (float*)d_out;

    prep_kernel<<<NBLK, 128>>>(x, mask, proj, score_src, score_tgt, skip_w);
    attn_kernel<<<N_NODES, 128>>>(bias, out);
}

// round 14
// speedup vs baseline: 1.2074x; 1.0112x over previous
#include <cuda_runtime.h>
#include <cuda_fp16.h>

#define N_NODES 4096
#define FIN     128
#define NH      4
#define FOUT    64
#define HF      256
#define MAXD    256
#define NBLK    1024   // even b -> GEMM (512), odd b -> scan (512, 8 rows each)

// -------- device scratch --------
__device__ __half g_h2[NH * N_NODES * FOUT];     // fp16 [h][n][f] (2 MB), 128B/row
__device__ float  g_ss[N_NODES * NH];            // src score [n][h]
__device__ float  g_st[N_NODES * NH];            // tgt score [n][h] (float4-loadable)
__device__ float  g_skip[N_NODES * HF];          // skip proj result
__device__ unsigned short g_adj[(size_t)N_NODES * MAXD];
__device__ int    g_deg[N_NODES];

static __device__ __forceinline__ unsigned pack_half2(float a, float b) {
    const __half2 h = __floats2half2_rn(a, b);
    return *(const unsigned*)&h;
}

union F2U { float2 f; unsigned long long u; };

static __device__ __forceinline__ void fma_f32x2(unsigned long long& acc,
                                                 unsigned long long a,
                                                 unsigned long long b) {
    asm("fma.rn.f32x2 %0, %1, %2, %0;" : "+l"(acc) : "l"(a), "l"(b));
}

// ============================================================
// Fat kernel. Even b: tensor-core GEMM tile (R11-proven paths).
// Odd b: mask scan, 8 rows per block (2 sequential rows/warp).
// 1024 blocks -> single wave at 32.5KB smem/block.
// ============================================================
__global__ __launch_bounds__(128) void prep_kernel(
    const float* __restrict__ x,
    const float* __restrict__ mask,
    const float* __restrict__ proj,
    const float* __restrict__ score_src,
    const float* __restrict__ score_tgt,
    const float* __restrict__ skip_w)
{
    __shared__ uint4 xs4[64 * 16];   // A tile (16 KB)
    __shared__ uint4 ws4[128 * 8];   // B tile (16 KB)
    __shared__ float redS[2][64], redT[2][64];

    const int b   = blockIdx.x;
    const int tid = threadIdx.x;

    if (b & 1) {
        // ---------------- scan role: 2 rows per warp ----------------
        const int sb   = b >> 1;                  // 0..511
        const int wid  = tid >> 5;
        const int lane = tid & 31;
        const unsigned lt = (1u << lane) - 1u;
#pragma unroll
        for (int p2 = 0; p2 < 2; p2++) {
            const int row = sb * 8 + p2 * 4 + wid;
            const float4* mr = (const float4*)(mask + (size_t)row * N_NODES);
            unsigned short* adj = g_adj + (size_t)row * MAXD;
            int base = 0;
#pragma unroll 16
            for (int g = 0; g < N_NODES / 128; g++) {
                const float4 v = mr[g * 32 + lane];
                const unsigned b0 = __ballot_sync(0xffffffffu, v.x == 0.f);
                const unsigned b1 = __ballot_sync(0xffffffffu, v.y == 0.f);
                const unsigned b2 = __ballot_sync(0xffffffffu, v.z == 0.f);
                const unsigned b3 = __ballot_sync(0xffffffffu, v.w == 0.f);
                const int c0 = __popc(b0), c1 = __popc(b1), c2 = __popc(b2), c3 = __popc(b3);
                const int e0 = g * 128 + lane * 4;
                if (v.x == 0.f) { int p = base + __popc(b0 & lt);                if (p < MAXD) adj[p] = (unsigned short)(e0);     }
                if (v.y == 0.f) { int p = base + c0 + __popc(b1 & lt);           if (p < MAXD) adj[p] = (unsigned short)(e0 + 1); }
                if (v.z == 0.f) { int p = base + c0 + c1 + __popc(b2 & lt);      if (p < MAXD) adj[p] = (unsigned short)(e0 + 2); }
                if (v.w == 0.f) { int p = base + c0 + c1 + c2 + __popc(b3 & lt); if (p < MAXD) adj[p] = (unsigned short)(e0 + 3); }
                base += c0 + c1 + c2 + c3;
            }
            if (lane == 0) g_deg[row] = min(base, MAXD);
        }
        return;
    }

    // ---------------- GEMM role ----------------
    const int gb = b >> 1;           // 0..511
    const int rt = gb >> 3;          // row tile 0..63
    const int ct = gb & 7;           // col tile 0..7
    const int r0 = rt * 64;
    const int w    = tid >> 5;       // warp 0..3
    const int lane = tid & 31;
    const int wr = (w >> 1) * 32;
    const int wc = (w & 1) * 32;

    // ---- stage A ----
    {
        const float4* xg = (const float4*)(x + (size_t)r0 * FIN);
#pragma unroll
        for (int i = 0; i < 8; i++) {
            const int idx = tid + i * 128;
            const int r = idx >> 4, c8 = idx & 15;
            const float4 v0 = xg[r * 32 + c8 * 2];
            const float4 v1 = xg[r * 32 + c8 * 2 + 1];
            uint4 pk;
            pk.x = pack_half2(v0.x, v0.y);
            pk.y = pack_half2(v0.z, v0.w);
            pk.z = pack_half2(v1.x, v1.y);
            pk.w = pack_half2(v1.z, v1.w);
            xs4[r * 16 + (c8 ^ (r & 7))] = pk;
        }
    }
    // ---- stage B ----
    if (ct >= 4) {
        const float4* wg = (const float4*)(skip_w + (size_t)((ct - 4) * 64) * FIN);
#pragma unroll
        for (int i = 0; i < 8; i++) {
            const int idx = tid + i * 128;
            const int r = idx >> 4, c8 = idx & 15;
            const float4 v0 = wg[r * 32 + c8 * 2];
            const float4 v1 = wg[r * 32 + c8 * 2 + 1];
            uint4 pk;
            pk.x = pack_half2(v0.x, v0.y);
            pk.y = pack_half2(v0.z, v0.w);
            pk.z = pack_half2(v1.x, v1.y);
            pk.w = pack_half2(v1.z, v1.w);
            ws4[r * 16 + (c8 ^ (r & 7))] = pk;
        }
    } else {
        const float4* pg = (const float4*)(proj + (size_t)ct * FIN * FOUT);
#pragma unroll
        for (int i = 0; i < 8; i++) {
            const int idx = tid + i * 128;
            const int r = idx >> 3, c8 = idx & 7;
            const float4 v0 = pg[r * 16 + c8 * 2];
            const float4 v1 = pg[r * 16 + c8 * 2 + 1];
            uint4 pk;
            pk.x = pack_half2(v0.x, v0.y);
            pk.y = pack_half2(v0.z, v0.w);
            pk.z = pack_half2(v1.x, v1.y);
            pk.w = pack_half2(v1.z, v1.w);
            ws4[r * 8 + (c8 ^ (r & 7))] = pk;
        }
    }
    __syncthreads();

    // ---- mma compute ----
    float acc[2][4][4];
#pragma unroll
    for (int mi = 0; mi < 2; mi++)
#pragma unroll
        for (int ni = 0; ni < 4; ni++)
#pragma unroll
            for (int t = 0; t < 4; t++) acc[mi][ni][t] = 0.f;

    const unsigned xsb = (unsigned)__cvta_generic_to_shared(xs4);
    const unsigned wsb = (unsigned)__cvta_generic_to_shared(ws4);

#pragma unroll
    for (int kc = 0; kc < 8; kc++) {
        unsigned a[2][4];
#pragma unroll
        for (int mi = 0; mi < 2; mi++) {
            const int rl = wr + mi * 16 + (lane & 15);
            const int ch = kc * 2 + (lane >> 4);
            const unsigned ad = xsb + rl * 256 + ((ch ^ (rl & 7)) << 4);
            asm volatile("ldmatrix.sync.aligned.m8n8.x4.shared.b16 {%0,%1,%2,%3}, [%4];"
                         : "=r"(a[mi][0]), "=r"(a[mi][1]), "=r"(a[mi][2]), "=r"(a[mi][3])
                         : "r"(ad));
        }
        unsigned bf[4][2];
        if (ct >= 4) {
#pragma unroll
            for (int ni = 0; ni < 4; ni++) {
                const int cl = wc + ni * 8 + (lane & 7);
                const int ch = kc * 2 + ((lane >> 3) & 1);
                const unsigned ad = wsb + cl * 256 + ((ch ^ (cl & 7)) << 4);
                asm volatile("ldmatrix.sync.aligned.m8n8.x2.shared.b16 {%0,%1}, [%2];"
                             : "=r"(bf[ni][0]), "=r"(bf[ni][1])
                             : "r"(ad));
            }
        } else {
#pragma unroll
            for (int ni = 0; ni < 4; ni++) {
                const int k  = kc * 16 + (lane & 15);
                const int c8 = (wc >> 3) + ni;
                const unsigned ad = wsb + (k * 8 + (c8 ^ (k & 7))) * 16;
                asm volatile("ldmatrix.sync.aligned.m8n8.x2.trans.shared.b16 {%0,%1}, [%2];"
                             : "=r"(bf[ni][0]), "=r"(bf[ni][1])
                             : "r"(ad));
            }
        }
#pragma unroll
        for (int mi = 0; mi < 2; mi++)
#pragma unroll
            for (int ni = 0; ni < 4; ni++)
                asm volatile("mma.sync.aligned.m16n8k16.row.col.f32.f16.f16.f32 "
                             "{%0,%1,%2,%3}, {%4,%5,%6,%7}, {%8,%9}, {%0,%1,%2,%3};"
                             : "+f"(acc[mi][ni][0]), "+f"(acc[mi][ni][1]),
                               "+f"(acc[mi][ni][2]), "+f"(acc[mi][ni][3])
                             : "r"(a[mi][0]), "r"(a[mi][1]), "r"(a[mi][2]), "r"(a[mi][3]),
                               "r"(bf[ni][0]), "r"(bf[ni][1]));
    }

    // ---- epilogue ----
    const int g   = lane >> 2;
    const int tig = lane & 3;
    if (ct < 4) {
        const int h = ct;
#pragma unroll
        for (int mi = 0; mi < 2; mi++) {
            const int lr1 = wr + mi * 16 + g;
            const int lr2 = lr1 + 8;
            float sS1 = 0.f, sT1 = 0.f, sS2 = 0.f, sT2 = 0.f;
#pragma unroll
            for (int ni = 0; ni < 4; ni++) {
                const int c0c = wc + ni * 8 + tig * 2;
                const float sv0 = score_src[h * FOUT + c0c];
                const float sv1 = score_src[h * FOUT + c0c + 1];
                const float tv0 = score_tgt[h * FOUT + c0c];
                const float tv1 = score_tgt[h * FOUT + c0c + 1];
                const float2 hi = {acc[mi][ni][0], acc[mi][ni][1]};
                const float2 lo = {acc[mi][ni][2], acc[mi][ni][3]};
                *(unsigned*)((char*)g_h2 + (((size_t)h * N_NODES + r0 + lr1) * FOUT + c0c) * 2) = pack_half2(hi.x, hi.y);
                *(unsigned*)((char*)g_h2 + (((size_t)h * N_NODES + r0 + lr2) * FOUT + c0c) * 2) = pack_half2(lo.x, lo.y);
                sS1 += hi.x * sv0 + hi.y * sv1;  sT1 += hi.x * tv0 + hi.y * tv1;
                sS2 += lo.x * sv0 + lo.y * sv1;  sT2 += lo.x * tv0 + lo.y * tv1;
            }
#pragma unroll
            for (int o = 1; o < 4; o <<= 1) {
                sS1 += __shfl_xor_sync(0xffffffffu, sS1, o);
                sT1 += __shfl_xor_sync(0xffffffffu, sT1, o);
                sS2 += __shfl_xor_sync(0xffffffffu, sS2, o);
                sT2 += __shfl_xor_sync(0xffffffffu, sT2, o);
            }
            if (tig == 0) {
                redS[w & 1][lr1] = sS1;  redT[w & 1][lr1] = sT1;
                redS[w & 1][lr2] = sS2;  redT[w & 1][lr2] = sT2;
            }
        }
        __syncthreads();
        if (tid < 64) {
            g_ss[(r0 + tid) * NH + h] = redS[0][tid] + redS[1][tid];
            g_st[(r0 + tid) * NH + h] = redT[0][tid] + redT[1][tid];
        }
    } else {
        const int c0g = (ct - 4) * 64;
#pragma unroll
        for (int mi = 0; mi < 2; mi++) {
            const int lr1 = wr + mi * 16 + g;
            const int lr2 = lr1 + 8;
#pragma unroll
            for (int ni = 0; ni < 4; ni++) {
                const int cc = c0g + wc + ni * 8 + tig * 2;
                const float2 hi = {acc[mi][ni][0], acc[mi][ni][1]};
                const float2 lo = {acc[mi][ni][2], acc[mi][ni][3]};
                *(float2*)(g_skip + (size_t)(r0 + lr1) * HF + cc) = hi;
                *(float2*)(g_skip + (size_t)(r0 + lr2) * HF + cc) = lo;
            }
        }
    }
}

// ============================================================
// Attention kernel (R13 structure; gather uses packed f32x2 FMA).
// ============================================================
__global__ __launch_bounds__(128) void attn_kernel(
    const float* __restrict__ bias,
    float* __restrict__ out)
{
    const int n    = blockIdx.x;
    const int tid  = threadIdx.x;
    const int h    = tid >> 5;
    const int lane = tid & 31;

    __shared__ float2 pair[NH][MAXD];
    __shared__ float  partS[NH][NH + 1];

    const int deg = g_deg[n];
    const float4 ss4 = *(const float4*)(g_ss + (size_t)n * NH);
    const float4* st4 = (const float4*)g_st;
    const unsigned short* adj = g_adj + (size_t)n * MAXD;

    float s0 = 0.f, s1 = 0.f, s2 = 0.f, s3 = 0.f;
    for (int j = tid; j < deg; j += 128) {
        const int m = adj[j];
        const float4 st = st4[m];
        float v0 = ss4.x + st.x; v0 = v0 > 0.f ? v0 : 0.2f * v0;
        float v1 = ss4.y + st.y; v1 = v1 > 0.f ? v1 : 0.2f * v1;
        float v2 = ss4.z + st.z; v2 = v2 > 0.f ? v2 : 0.2f * v2;
        float v3 = ss4.w + st.w; v3 = v3 > 0.f ? v3 : 0.2f * v3;
        const float e0 = __expf(v0), e1 = __expf(v1);
        const float e2 = __expf(v2), e3 = __expf(v3);
        const float fo = __int_as_float(m * (FOUT * 2));   // byte offset of fp16 row
        pair[0][j] = make_float2(e0, fo);
        pair[1][j] = make_float2(e1, fo);
        pair[2][j] = make_float2(e2, fo);
        pair[3][j] = make_float2(e3, fo);
        s0 += e0; s1 += e1; s2 += e2; s3 += e3;
    }
#pragma unroll
    for (int o = 16; o; o >>= 1) {
        s0 += __shfl_xor_sync(0xffffffffu, s0, o);
        s1 += __shfl_xor_sync(0xffffffffu, s1, o);
        s2 += __shfl_xor_sync(0xffffffffu, s2, o);
        s3 += __shfl_xor_sync(0xffffffffu, s3, o);
    }
    if (lane == 0) {
        partS[h][0] = s0; partS[h][1] = s1;
        partS[h][2] = s2; partS[h][3] = s3;
    }
    __syncthreads();
    const float S = partS[0][h] + partS[1][h] + partS[2][h] + partS[3][h];

    // gather: subgroup g of 16 lanes handles j = g, g+2, ...; lane q -> 8 bytes (4 halves)
    const int g = lane >> 4;
    const int q = lane & 15;
    const char* hb = (const char*)g_h2 + (size_t)h * N_NODES * (FOUT * 2) + q * 8;
    unsigned long long accA0 = 0, accA1 = 0, accB0 = 0, accB1 = 0;  // packed {f32,f32} zeros
    int j = g;
    for (; j + 6 < deg; j += 8) {
        const float2 p0 = pair[h][j];
        const float2 p1 = pair[h][j + 2];
        const float2 p2 = pair[h][j + 4];
        const float2 p3 = pair[h][j + 6];
        const uint2 h0 = *(const uint2*)(hb + __float_as_int(p0.y));
        const uint2 h1 = *(const uint2*)(hb + __float_as_int(p1.y));
        const uint2 h2 = *(const uint2*)(hb + __float_as_int(p2.y));
        const uint2 h3 = *(const uint2*)(hb + __float_as_int(p3.y));
        F2U pp0; pp0.f = make_float2(p0.x, p0.x);
        F2U pp1; pp1.f = make_float2(p1.x, p1.x);
        F2U pp2; pp2.f = make_float2(p2.x, p2.x);
        F2U pp3; pp3.f = make_float2(p3.x, p3.x);
        F2U v00; v00.f = __half22float2(*(const __half2*)&h0.x);
        F2U v01; v01.f = __half22float2(*(const __half2*)&h0.y);
        F2U v10; v10.f = __half22float2(*(const __half2*)&h1.x);
        F2U v11; v11.f = __half22float2(*(const __half2*)&h1.y);
        F2U v20; v20.f = __half22float2(*(const __half2*)&h2.x);
        F2U v21; v21.f = __half22float2(*(const __half2*)&h2.y);
        F2U v30; v30.f = __half22float2(*(const __half2*)&h3.x);
        F2U v31; v31.f = __half22float2(*(const __half2*)&h3.y);
        fma_f32x2(accA0, pp0.u, v00.u);  fma_f32x2(accA1, pp0.u, v01.u);
        fma_f32x2(accB0, pp1.u, v10.u);  fma_f32x2(accB1, pp1.u, v11.u);
        fma_f32x2(accA0, pp2.u, v20.u);  fma_f32x2(accA1, pp2.u, v21.u);
        fma_f32x2(accB0, pp3.u, v30.u);  fma_f32x2(accB1, pp3.u, v31.u);
    }
    for (; j < deg; j += 2) {
        const float2 pr = pair[h][j];
        const uint2 hv = *(const uint2*)(hb + __float_as_int(pr.y));
        F2U pp; pp.f = make_float2(pr.x, pr.x);
        F2U v0; v0.f = __half22float2(*(const __half2*)&hv.x);
        F2U v1; v1.f = __half22float2(*(const __half2*)&hv.y);
        fma_f32x2(accA0, pp.u, v0.u);
        fma_f32x2(accA1, pp.u, v1.u);
    }
    F2U rA0; rA0.u = accA0;  F2U rA1; rA1.u = accA1;
    F2U rB0; rB0.u = accB0;  F2U rB1; rB1.u = accB1;
    float4 a = {rA0.f.x + rB0.f.x, rA0.f.y + rB0.f.y,
                rA1.f.x + rB1.f.x, rA1.f.y + rB1.f.y};
    a.x += __shfl_xor_sync(0xffffffffu, a.x, 16);
    a.y += __shfl_xor_sync(0xffffffffu, a.y, 16);
    a.z += __shfl_xor_sync(0xffffffffu, a.z, 16);
    a.w += __shfl_xor_sync(0xffffffffu, a.w, 16);

    if (g == 0) {
        const float inv = 1.f / S;
        const int c4 = h * 16 + q;
        const float4 sk = ((const float4*)(g_skip + (size_t)n * HF))[c4];
        const float4 bi = ((const float4*)bias)[c4];
        float o0 = a.x * inv + sk.x + bi.x;
        float o1 = a.y * inv + sk.y + bi.y;
        float o2 = a.z * inv + sk.z + bi.z;
        float o3 = a.w * inv + sk.w + bi.w;
        o0 = o0 > 0.f ? o0 : (__expf(o0) - 1.f);
        o1 = o1 > 0.f ? o1 : (__expf(o1) - 1.f);
        o2 = o2 > 0.f ? o2 : (__expf(o2) - 1.f);
        o3 = o3 > 0.f ? o3 : (__expf(o3) - 1.f);
        const float4 res = {o0, o1, o2, o3};
        ((float4*)(out + (size_t)n * HF))[c4] = res;
    }
}

// ============================================================
extern "C" void kernel_launch(void* const* d_in, const int* in_sizes, int n_in,
                              void* d_out, int out_size)
{
    const float* x         = (const float*)d_in[0];
    const float* mask      = (const float*)d_in[1];
    const float* proj      = (const float*)d_in[2];
    const float* score_src = (const float*)d_in[3];
    const float* score_tgt = (const float*)d_in[4];
    const float* skip_w    = (const float*)d_in[5];
    const float* bias      = (const float*)d_in[6];
    float* out             = (float*)d_out;

    prep_kernel<<<NBLK, 128>>>(x, mask, proj, score_src, score_tgt, skip_w);
    attn_kernel<<<N_NODES, 128>>>(bias, out);
}

// round 15
// speedup vs baseline: 1.3171x; 1.0908x over previous
#include <cuda_runtime.h>
#include <cuda_fp16.h>

#define N_NODES 4096
#define FIN     128
#define NH      4
#define FOUT    64
#define HF      256
#define MAXD    256
#define NBLK    1536   // b%3 in {0,1} -> scan (1024 blocks, 1 row/warp), b%3==2 -> GEMM (512)

// -------- device scratch --------
__device__ __half g_h2[NH * N_NODES * FOUT];     // fp16 [h][n][f] (2 MB), 128B/row
__device__ float  g_ss[N_NODES * NH];            // src score [n][h]
__device__ float  g_st[N_NODES * NH];            // tgt score [n][h] (float4-loadable)
__device__ float  g_skip[N_NODES * HF];          // skip proj result
__device__ unsigned short g_adj[(size_t)N_NODES * MAXD];
__device__ int    g_deg[N_NODES];

static __device__ __forceinline__ unsigned pack_half2(float a, float b) {
    const __half2 h = __floats2half2_rn(a, b);
    return *(const unsigned*)&h;
}

union F2U { float2 f; unsigned long long u; };

static __device__ __forceinline__ void fma_f32x2(unsigned long long& acc,
                                                 unsigned long long a,
                                                 unsigned long long b) {
    asm("fma.rn.f32x2 %0, %1, %2, %0;" : "+l"(acc) : "l"(a), "l"(b));
}

// ============================================================
// Fat kernel (R13-proven layout). b%3==2: tensor-core GEMM tile;
// else: mask scan, warp per row (4 rows/block, 1024 scan blocks).
// ============================================================
__global__ __launch_bounds__(128) void prep_kernel(
    const float* __restrict__ x,
    const float* __restrict__ mask,
    const float* __restrict__ proj,
    const float* __restrict__ score_src,
    const float* __restrict__ score_tgt,
    const float* __restrict__ skip_w)
{
    __shared__ uint4 xs4[64 * 16];   // A tile (16 KB)
    __shared__ uint4 ws4[128 * 8];   // B tile (16 KB)
    __shared__ float redS[2][64], redT[2][64];

    const int b   = blockIdx.x;
    const int tid = threadIdx.x;

    if (b % 3 != 2) {
        // ---------------- scan role: warp per row ----------------
        const int sb   = (b / 3) * 2 + (b % 3);    // 0..1023
        const int wid  = tid >> 5;
        const int lane = tid & 31;
        const int row  = sb * 4 + wid;
        const float4* mr = (const float4*)(mask + (size_t)row * N_NODES);
        unsigned short* adj = g_adj + (size_t)row * MAXD;
        const unsigned lt = (1u << lane) - 1u;
        int base = 0;
#pragma unroll 16
        for (int g = 0; g < N_NODES / 128; g++) {
            const float4 v = mr[g * 32 + lane];
            const unsigned b0 = __ballot_sync(0xffffffffu, v.x == 0.f);
            const unsigned b1 = __ballot_sync(0xffffffffu, v.y == 0.f);
            const unsigned b2 = __ballot_sync(0xffffffffu, v.z == 0.f);
            const unsigned b3 = __ballot_sync(0xffffffffu, v.w == 0.f);
            const int c0 = __popc(b0), c1 = __popc(b1), c2 = __popc(b2), c3 = __popc(b3);
            const int e0 = g * 128 + lane * 4;
            if (v.x == 0.f) { int p = base + __popc(b0 & lt);                if (p < MAXD) adj[p] = (unsigned short)(e0);     }
            if (v.y == 0.f) { int p = base + c0 + __popc(b1 & lt);           if (p < MAXD) adj[p] = (unsigned short)(e0 + 1); }
            if (v.z == 0.f) { int p = base + c0 + c1 + __popc(b2 & lt);      if (p < MAXD) adj[p] = (unsigned short)(e0 + 2); }
            if (v.w == 0.f) { int p = base + c0 + c1 + c2 + __popc(b3 & lt); if (p < MAXD) adj[p] = (unsigned short)(e0 + 3); }
            base += c0 + c1 + c2 + c3;
        }
        if (lane == 0) g_deg[row] = min(base, MAXD);
        return;
    }

    // ---------------- GEMM role ----------------
    const int gb = b / 3;            // 0..511
    const int rt = gb >> 3;          // row tile 0..63
    const int ct = gb & 7;           // col tile 0..7
    const int r0 = rt * 64;
    const int w    = tid >> 5;       // warp 0..3
    const int lane = tid & 31;
    const int wr = (w >> 1) * 32;
    const int wc = (w & 1) * 32;

    // ---- stage A ----
    {
        const float4* xg = (const float4*)(x + (size_t)r0 * FIN);
#pragma unroll
        for (int i = 0; i < 8; i++) {
            const int idx = tid + i * 128;
            const int r = idx >> 4, c8 = idx & 15;
            const float4 v0 = xg[r * 32 + c8 * 2];
            const float4 v1 = xg[r * 32 + c8 * 2 + 1];
            uint4 pk;
            pk.x = pack_half2(v0.x, v0.y);
            pk.y = pack_half2(v0.z, v0.w);
            pk.z = pack_half2(v1.x, v1.y);
            pk.w = pack_half2(v1.z, v1.w);
            xs4[r * 16 + (c8 ^ (r & 7))] = pk;
        }
    }
    // ---- stage B ----
    if (ct >= 4) {
        const float4* wg = (const float4*)(skip_w + (size_t)((ct - 4) * 64) * FIN);
#pragma unroll
        for (int i = 0; i < 8; i++) {
            const int idx = tid + i * 128;
            const int r = idx >> 4, c8 = idx & 15;
            const float4 v0 = wg[r * 32 + c8 * 2];
            const float4 v1 = wg[r * 32 + c8 * 2 + 1];
            uint4 pk;
            pk.x = pack_half2(v0.x, v0.y);
            pk.y = pack_half2(v0.z, v0.w);
            pk.z = pack_half2(v1.x, v1.y);
            pk.w = pack_half2(v1.z, v1.w);
            ws4[r * 16 + (c8 ^ (r & 7))] = pk;
        }
    } else {
        const float4* pg = (const float4*)(proj + (size_t)ct * FIN * FOUT);
#pragma unroll
        for (int i = 0; i < 8; i++) {
            const int idx = tid + i * 128;
            const int r = idx >> 3, c8 = idx & 7;
            const float4 v0 = pg[r * 16 + c8 * 2];
            const float4 v1 = pg[r * 16 + c8 * 2 + 1];
            uint4 pk;
            pk.x = pack_half2(v0.x, v0.y);
            pk.y = pack_half2(v0.z, v0.w);
            pk.z = pack_half2(v1.x, v1.y);
            pk.w = pack_half2(v1.z, v1.w);
            ws4[r * 8 + (c8 ^ (r & 7))] = pk;
        }
    }
    __syncthreads();

    // ---- mma compute ----
    float acc[2][4][4];
#pragma unroll
    for (int mi = 0; mi < 2; mi++)
#pragma unroll
        for (int ni = 0; ni < 4; ni++)
#pragma unroll
            for (int t = 0; t < 4; t++) acc[mi][ni][t] = 0.f;

    const unsigned xsb = (unsigned)__cvta_generic_to_shared(xs4);
    const unsigned wsb = (unsigned)__cvta_generic_to_shared(ws4);

#pragma unroll
    for (int kc = 0; kc < 8; kc++) {
        unsigned a[2][4];
#pragma unroll
        for (int mi = 0; mi < 2; mi++) {
            const int rl = wr + mi * 16 + (lane & 15);
            const int ch = kc * 2 + (lane >> 4);
            const unsigned ad = xsb + rl * 256 + ((ch ^ (rl & 7)) << 4);
            asm volatile("ldmatrix.sync.aligned.m8n8.x4.shared.b16 {%0,%1,%2,%3}, [%4];"
                         : "=r"(a[mi][0]), "=r"(a[mi][1]), "=r"(a[mi][2]), "=r"(a[mi][3])
                         : "r"(ad));
        }
        unsigned bf[4][2];
        if (ct >= 4) {
#pragma unroll
            for (int ni = 0; ni < 4; ni++) {
                const int cl = wc + ni * 8 + (lane & 7);
                const int ch = kc * 2 + ((lane >> 3) & 1);
                const unsigned ad = wsb + cl * 256 + ((ch ^ (cl & 7)) << 4);
                asm volatile("ldmatrix.sync.aligned.m8n8.x2.shared.b16 {%0,%1}, [%2];"
                             : "=r"(bf[ni][0]), "=r"(bf[ni][1])
                             : "r"(ad));
            }
        } else {
#pragma unroll
            for (int ni = 0; ni < 4; ni++) {
                const int k  = kc * 16 + (lane & 15);
                const int c8 = (wc >> 3) + ni;
                const unsigned ad = wsb + (k * 8 + (c8 ^ (k & 7))) * 16;
                asm volatile("ldmatrix.sync.aligned.m8n8.x2.trans.shared.b16 {%0,%1}, [%2];"
                             : "=r"(bf[ni][0]), "=r"(bf[ni][1])
                             : "r"(ad));
            }
        }
#pragma unroll
        for (int mi = 0; mi < 2; mi++)
#pragma unroll
            for (int ni = 0; ni < 4; ni++)
                asm volatile("mma.sync.aligned.m16n8k16.row.col.f32.f16.f16.f32 "
                             "{%0,%1,%2,%3}, {%4,%5,%6,%7}, {%8,%9}, {%0,%1,%2,%3};"
                             : "+f"(acc[mi][ni][0]), "+f"(acc[mi][ni][1]),
                               "+f"(acc[mi][ni][2]), "+f"(acc[mi][ni][3])
                             : "r"(a[mi][0]), "r"(a[mi][1]), "r"(a[mi][2]), "r"(a[mi][3]),
                               "r"(bf[ni][0]), "r"(bf[ni][1]));
    }

    // ---- epilogue ----
    const int g   = lane >> 2;
    const int tig = lane & 3;
    if (ct < 4) {
        const int h = ct;
#pragma unroll
        for (int mi = 0; mi < 2; mi++) {
            const int lr1 = wr + mi * 16 + g;
            const int lr2 = lr1 + 8;
            float sS1 = 0.f, sT1 = 0.f, sS2 = 0.f, sT2 = 0.f;
#pragma unroll
            for (int ni = 0; ni < 4; ni++) {
                const int c0c = wc + ni * 8 + tig * 2;
                const float sv0 = score_src[h * FOUT + c0c];
                const float sv1 = score_src[h * FOUT + c0c + 1];
                const float tv0 = score_tgt[h * FOUT + c0c];
                const float tv1 = score_tgt[h * FOUT + c0c + 1];
                const float2 hi = {acc[mi][ni][0], acc[mi][ni][1]};
                const float2 lo = {acc[mi][ni][2], acc[mi][ni][3]};
                *(unsigned*)((char*)g_h2 + (((size_t)h * N_NODES + r0 + lr1) * FOUT + c0c) * 2) = pack_half2(hi.x, hi.y);
                *(unsigned*)((char*)g_h2 + (((size_t)h * N_NODES + r0 + lr2) * FOUT + c0c) * 2) = pack_half2(lo.x, lo.y);
                sS1 += hi.x * sv0 + hi.y * sv1;  sT1 += hi.x * tv0 + hi.y * tv1;
                sS2 += lo.x * sv0 + lo.y * sv1;  sT2 += lo.x * tv0 + lo.y * tv1;
            }
#pragma unroll
            for (int o = 1; o < 4; o <<= 1) {
                sS1 += __shfl_xor_sync(0xffffffffu, sS1, o);
                sT1 += __shfl_xor_sync(0xffffffffu, sT1, o);
                sS2 += __shfl_xor_sync(0xffffffffu, sS2, o);
                sT2 += __shfl_xor_sync(0xffffffffu, sT2, o);
            }
            if (tig == 0) {
                redS[w & 1][lr1] = sS1;  redT[w & 1][lr1] = sT1;
                redS[w & 1][lr2] = sS2;  redT[w & 1][lr2] = sT2;
            }
        }
        __syncthreads();
        if (tid < 64) {
            g_ss[(r0 + tid) * NH + h] = redS[0][tid] + redS[1][tid];
            g_st[(r0 + tid) * NH + h] = redT[0][tid] + redT[1][tid];
        }
    } else {
        const int c0g = (ct - 4) * 64;
#pragma unroll
        for (int mi = 0; mi < 2; mi++) {
            const int lr1 = wr + mi * 16 + g;
            const int lr2 = lr1 + 8;
#pragma unroll
            for (int ni = 0; ni < 4; ni++) {
                const int cc = c0g + wc + ni * 8 + tig * 2;
                const float2 hi = {acc[mi][ni][0], acc[mi][ni][1]};
                const float2 lo = {acc[mi][ni][2], acc[mi][ni][3]};
                *(float2*)(g_skip + (size_t)(r0 + lr1) * HF + cc) = hi;
                *(float2*)(g_skip + (size_t)(r0 + lr2) * HF + cc) = lo;
            }
        }
    }
}

// ============================================================
// Attention kernel (R14-proven: fp16 gathers + packed f32x2 FMA).
// ============================================================
__global__ __launch_bounds__(128) void attn_kernel(
    const float* __restrict__ bias,
    float* __restrict__ out)
{
    const int n    = blockIdx.x;
    const int tid  = threadIdx.x;
    const int h    = tid >> 5;
    const int lane = tid & 31;

    __shared__ float2 pair[NH][MAXD];
    __shared__ float  partS[NH][NH + 1];

    const int deg = g_deg[n];
    const float4 ss4 = *(const float4*)(g_ss + (size_t)n * NH);
    const float4* st4 = (const float4*)g_st;
    const unsigned short* adj = g_adj + (size_t)n * MAXD;

    float s0 = 0.f, s1 = 0.f, s2 = 0.f, s3 = 0.f;
    for (int j = tid; j < deg; j += 128) {
        const int m = adj[j];
        const float4 st = st4[m];
        float v0 = ss4.x + st.x; v0 = v0 > 0.f ? v0 : 0.2f * v0;
        float v1 = ss4.y + st.y; v1 = v1 > 0.f ? v1 : 0.2f * v1;
        float v2 = ss4.z + st.z; v2 = v2 > 0.f ? v2 : 0.2f * v2;
        float v3 = ss4.w + st.w; v3 = v3 > 0.f ? v3 : 0.2f * v3;
        const float e0 = __expf(v0), e1 = __expf(v1);
        const float e2 = __expf(v2), e3 = __expf(v3);
        const float fo = __int_as_float(m * (FOUT * 2));   // byte offset of fp16 row
        pair[0][j] = make_float2(e0, fo);
        pair[1][j] = make_float2(e1, fo);
        pair[2][j] = make_float2(e2, fo);
        pair[3][j] = make_float2(e3, fo);
        s0 += e0; s1 += e1; s2 += e2; s3 += e3;
    }
#pragma unroll
    for (int o = 16; o; o >>= 1) {
        s0 += __shfl_xor_sync(0xffffffffu, s0, o);
        s1 += __shfl_xor_sync(0xffffffffu, s1, o);
        s2 += __shfl_xor_sync(0xffffffffu, s2, o);
        s3 += __shfl_xor_sync(0xffffffffu, s3, o);
    }
    if (lane == 0) {
        partS[h][0] = s0; partS[h][1] = s1;
        partS[h][2] = s2; partS[h][3] = s3;
    }
    __syncthreads();
    const float S = partS[0][h] + partS[1][h] + partS[2][h] + partS[3][h];

    // gather: subgroup g of 16 lanes handles j = g, g+2, ...; lane q -> 8 bytes (4 halves)
    const int g = lane >> 4;
    const int q = lane & 15;
    const char* hb = (const char*)g_h2 + (size_t)h * N_NODES * (FOUT * 2) + q * 8;
    unsigned long long accA0 = 0, accA1 = 0, accB0 = 0, accB1 = 0;
    int j = g;
    for (; j + 6 < deg; j += 8) {
        const float2 p0 = pair[h][j];
        const float2 p1 = pair[h][j + 2];
        const float2 p2 = pair[h][j + 4];
        const float2 p3 = pair[h][j + 6];
        const uint2 h0 = *(const uint2*)(hb + __float_as_int(p0.y));
        const uint2 h1 = *(const uint2*)(hb + __float_as_int(p1.y));
        const uint2 h2 = *(const uint2*)(hb + __float_as_int(p2.y));
        const uint2 h3 = *(const uint2*)(hb + __float_as_int(p3.y));
        F2U pp0; pp0.f = make_float2(p0.x, p0.x);
        F2U pp1; pp1.f = make_float2(p1.x, p1.x);
        F2U pp2; pp2.f = make_float2(p2.x, p2.x);
        F2U pp3; pp3.f = make_float2(p3.x, p3.x);
        F2U v00; v00.f = __half22float2(*(const __half2*)&h0.x);
        F2U v01; v01.f = __half22float2(*(const __half2*)&h0.y);
        F2U v10; v10.f = __half22float2(*(const __half2*)&h1.x);
        F2U v11; v11.f = __half22float2(*(const __half2*)&h1.y);
        F2U v20; v20.f = __half22float2(*(const __half2*)&h2.x);
        F2U v21; v21.f = __half22float2(*(const __half2*)&h2.y);
        F2U v30; v30.f = __half22float2(*(const __half2*)&h3.x);
        F2U v31; v31.f = __half22float2(*(const __half2*)&h3.y);
        fma_f32x2(accA0, pp0.u, v00.u);  fma_f32x2(accA1, pp0.u, v01.u);
        fma_f32x2(accB0, pp1.u, v10.u);  fma_f32x2(accB1, pp1.u, v11.u);
        fma_f32x2(accA0, pp2.u, v20.u);  fma_f32x2(accA1, pp2.u, v21.u);
        fma_f32x2(accB0, pp3.u, v30.u);  fma_f32x2(accB1, pp3.u, v31.u);
    }
    for (; j < deg; j += 2) {
        const float2 pr = pair[h][j];
        const uint2 hv = *(const uint2*)(hb + __float_as_int(pr.y));
        F2U pp; pp.f = make_float2(pr.x, pr.x);
        F2U v0; v0.f = __half22float2(*(const __half2*)&hv.x);
        F2U v1; v1.f = __half22float2(*(const __half2*)&hv.y);
        fma_f32x2(accA0, pp.u, v0.u);
        fma_f32x2(accA1, pp.u, v1.u);
    }
    F2U rA0; rA0.u = accA0;  F2U rA1; rA1.u = accA1;
    F2U rB0; rB0.u = accB0;  F2U rB1; rB1.u = accB1;
    float4 a = {rA0.f.x + rB0.f.x, rA0.f.y + rB0.f.y,
                rA1.f.x + rB1.f.x, rA1.f.y + rB1.f.y};
    a.x += __shfl_xor_sync(0xffffffffu, a.x, 16);
    a.y += __shfl_xor_sync(0xffffffffu, a.y, 16);
    a.z += __shfl_xor_sync(0xffffffffu, a.z, 16);
    a.w += __shfl_xor_sync(0xffffffffu, a.w, 16);

    if (g == 0) {
        const float inv = 1.f / S;
        const int c4 = h * 16 + q;
        const float4 sk = ((const float4*)(g_skip + (size_t)n * HF))[c4];
        const float4 bi = ((const float4*)bias)[c4];
        float o0 = a.x * inv + sk.x + bi.x;
        float o1 = a.y * inv + sk.y + bi.y;
        float o2 = a.z * inv + sk.z + bi.z;
        float o3 = a.w * inv + sk.w + bi.w;
        o0 = o0 > 0.f ? o0 : (__expf(o0) - 1.f);
        o1 = o1 > 0.f ? o1 : (__expf(o1) - 1.f);
        o2 = o2 > 0.f ? o2 : (__expf(o2) - 1.f);
        o3 = o3 > 0.f ? o3 : (__expf(o3) - 1.f);
        const float4 res = {o0, o1, o2, o3};
        ((float4*)(out + (size_t)n * HF))[c4] = res;
    }
}

// ============================================================
extern "C" void kernel_launch(void* const* d_in, const int* in_sizes, int n_in,
                              void* d_out, int out_size)
{
    const float* x         = (const float*)d_in[0];
    const float* mask      = (const float*)d_in[1];
    const float* proj      = (const float*)d_in[2];
    const float* score_src = (const float*)d_in[3];
    const float* score_tgt = (const float*)d_in[4];
    const float* skip_w    = (const float*)d_in[5];
    const float* bias      = (const float*)d_in[6];
    float* out             = (float*)d_out;

    prep_kernel<<<NBLK, 128>>>(x, mask, proj, score_src, score_tgt, skip_w);
    attn_kernel<<<N_NODES, 128>>>(bias, out);
}

// round 16
// speedup vs baseline: 1.3193x; 1.0016x over previous
#include <cuda_runtime.h>
#include <cuda_fp16.h>

#define N_NODES 4096
#define FIN     128
#define NH      4
#define FOUT    64
#define HF      256
#define MAXD    256
#define NBLK    1536   // b%3 in {0,1} -> scan (1024 blocks, 1 row/warp), b%3==2 -> GEMM (512)
#define ESCALE  (1.0f / 4096.0f)

// -------- device scratch --------
__device__ __half g_h2[NH * N_NODES * FOUT];     // fp16 [h][n][f] (2 MB), 128B/row
__device__ float  g_ss[N_NODES * NH];            // src score [n][h]
__device__ float  g_st[N_NODES * NH];            // tgt score [n][h] (float4-loadable)
__device__ float  g_skip[N_NODES * HF];          // skip proj result
__device__ unsigned short g_adj[(size_t)N_NODES * MAXD];
__device__ int    g_deg[N_NODES];

static __device__ __forceinline__ unsigned pack_half2(float a, float b) {
    const __half2 h = __floats2half2_rn(a, b);
    return *(const unsigned*)&h;
}

union F2U { float2 f; unsigned long long u; };

static __device__ __forceinline__ void add_f32x2(unsigned long long& acc,
                                                 unsigned long long v) {
    asm("add.rn.f32x2 %0, %1, %0;" : "+l"(acc) : "l"(v));
}

static __device__ __forceinline__ __half2 u2h(unsigned u) {
    return *(const __half2*)&u;
}

// ============================================================
// Fat kernel (R15-proven, unchanged). b%3==2: tensor-core GEMM;
// else: mask scan, warp per row.
// ============================================================
__global__ __launch_bounds__(128) void prep_kernel(
    const float* __restrict__ x,
    const float* __restrict__ mask,
    const float* __restrict__ proj,
    const float* __restrict__ score_src,
    const float* __restrict__ score_tgt,
    const float* __restrict__ skip_w)
{
    __shared__ uint4 xs4[64 * 16];   // A tile (16 KB)
    __shared__ uint4 ws4[128 * 8];   // B tile (16 KB)
    __shared__ float redS[2][64], redT[2][64];

    const int b   = blockIdx.x;
    const int tid = threadIdx.x;

    if (b % 3 != 2) {
        // ---------------- scan role: warp per row ----------------
        const int sb   = (b / 3) * 2 + (b % 3);    // 0..1023
        const int wid  = tid >> 5;
        const int lane = tid & 31;
        const int row  = sb * 4 + wid;
        const float4* mr = (const float4*)(mask + (size_t)row * N_NODES);
        unsigned short* adj = g_adj + (size_t)row * MAXD;
        const unsigned lt = (1u << lane) - 1u;
        int base = 0;
#pragma unroll 16
        for (int g = 0; g < N_NODES / 128; g++) {
            const float4 v = mr[g * 32 + lane];
            const unsigned b0 = __ballot_sync(0xffffffffu, v.x == 0.f);
            const unsigned b1 = __ballot_sync(0xffffffffu, v.y == 0.f);
            const unsigned b2 = __ballot_sync(0xffffffffu, v.z == 0.f);
            const unsigned b3 = __ballot_sync(0xffffffffu, v.w == 0.f);
            const int c0 = __popc(b0), c1 = __popc(b1), c2 = __popc(b2), c3 = __popc(b3);
            const int e0 = g * 128 + lane * 4;
            if (v.x == 0.f) { int p = base + __popc(b0 & lt);                if (p < MAXD) adj[p] = (unsigned short)(e0);     }
            if (v.y == 0.f) { int p = base + c0 + __popc(b1 & lt);           if (p < MAXD) adj[p] = (unsigned short)(e0 + 1); }
            if (v.z == 0.f) { int p = base + c0 + c1 + __popc(b2 & lt);      if (p < MAXD) adj[p] = (unsigned short)(e0 + 2); }
            if (v.w == 0.f) { int p = base + c0 + c1 + c2 + __popc(b3 & lt); if (p < MAXD) adj[p] = (unsigned short)(e0 + 3); }
            base += c0 + c1 + c2 + c3;
        }
        if (lane == 0) g_deg[row] = min(base, MAXD);
        return;
    }

    // ---------------- GEMM role ----------------
    const int gb = b / 3;            // 0..511
    const int rt = gb >> 3;          // row tile 0..63
    const int ct = gb & 7;           // col tile 0..7
    const int r0 = rt * 64;
    const int w    = tid >> 5;       // warp 0..3
    const int lane = tid & 31;
    const int wr = (w >> 1) * 32;
    const int wc = (w & 1) * 32;

    // ---- stage A ----
    {
        const float4* xg = (const float4*)(x + (size_t)r0 * FIN);
#pragma unroll
        for (int i = 0; i < 8; i++) {
            const int idx = tid + i * 128;
            const int r = idx >> 4, c8 = idx & 15;
            const float4 v0 = xg[r * 32 + c8 * 2];
            const float4 v1 = xg[r * 32 + c8 * 2 + 1];
            uint4 pk;
            pk.x = pack_half2(v0.x, v0.y);
            pk.y = pack_half2(v0.z, v0.w);
            pk.z = pack_half2(v1.x, v1.y);
            pk.w = pack_half2(v1.z, v1.w);
            xs4[r * 16 + (c8 ^ (r & 7))] = pk;
        }
    }
    // ---- stage B ----
    if (ct >= 4) {
        const float4* wg = (const float4*)(skip_w + (size_t)((ct - 4) * 64) * FIN);
#pragma unroll
        for (int i = 0; i < 8; i++) {
            const int idx = tid + i * 128;
            const int r = idx >> 4, c8 = idx & 15;
            const float4 v0 = wg[r * 32 + c8 * 2];
            const float4 v1 = wg[r * 32 + c8 * 2 + 1];
            uint4 pk;
            pk.x = pack_half2(v0.x, v0.y);
            pk.y = pack_half2(v0.z, v0.w);
            pk.z = pack_half2(v1.x, v1.y);
            pk.w = pack_half2(v1.z, v1.w);
            ws4[r * 16 + (c8 ^ (r & 7))] = pk;
        }
    } else {
        const float4* pg = (const float4*)(proj + (size_t)ct * FIN * FOUT);
#pragma unroll
        for (int i = 0; i < 8; i++) {
            const int idx = tid + i * 128;
            const int r = idx >> 3, c8 = idx & 7;
            const float4 v0 = pg[r * 16 + c8 * 2];
            const float4 v1 = pg[r * 16 + c8 * 2 + 1];
            uint4 pk;
            pk.x = pack_half2(v0.x, v0.y);
            pk.y = pack_half2(v0.z, v0.w);
            pk.z = pack_half2(v1.x, v1.y);
            pk.w = pack_half2(v1.z, v1.w);
            ws4[r * 8 + (c8 ^ (r & 7))] = pk;
        }
    }
    __syncthreads();

    // ---- mma compute ----
    float acc[2][4][4];
#pragma unroll
    for (int mi = 0; mi < 2; mi++)
#pragma unroll
        for (int ni = 0; ni < 4; ni++)
#pragma unroll
            for (int t = 0; t < 4; t++) acc[mi][ni][t] = 0.f;

    const unsigned xsb = (unsigned)__cvta_generic_to_shared(xs4);
    const unsigned wsb = (unsigned)__cvta_generic_to_shared(ws4);

#pragma unroll
    for (int kc = 0; kc < 8; kc++) {
        unsigned a[2][4];
#pragma unroll
        for (int mi = 0; mi < 2; mi++) {
            const int rl = wr + mi * 16 + (lane & 15);
            const int ch = kc * 2 + (lane >> 4);
            const unsigned ad = xsb + rl * 256 + ((ch ^ (rl & 7)) << 4);
            asm volatile("ldmatrix.sync.aligned.m8n8.x4.shared.b16 {%0,%1,%2,%3}, [%4];"
                         : "=r"(a[mi][0]), "=r"(a[mi][1]), "=r"(a[mi][2]), "=r"(a[mi][3])
                         : "r"(ad));
        }
        unsigned bf[4][2];
        if (ct >= 4) {
#pragma unroll
            for (int ni = 0; ni < 4; ni++) {
                const int cl = wc + ni * 8 + (lane & 7);
                const int ch = kc * 2 + ((lane >> 3) & 1);
                const unsigned ad = wsb + cl * 256 + ((ch ^ (cl & 7)) << 4);
                asm volatile("ldmatrix.sync.aligned.m8n8.x2.shared.b16 {%0,%1}, [%2];"
                             : "=r"(bf[ni][0]), "=r"(bf[ni][1])
                             : "r"(ad));
            }
        } else {
#pragma unroll
            for (int ni = 0; ni < 4; ni++) {
                const int k  = kc * 16 + (lane & 15);
                const int c8 = (wc >> 3) + ni;
                const unsigned ad = wsb + (k * 8 + (c8 ^ (k & 7))) * 16;
                asm volatile("ldmatrix.sync.aligned.m8n8.x2.trans.shared.b16 {%0,%1}, [%2];"
                             : "=r"(bf[ni][0]), "=r"(bf[ni][1])
                             : "r"(ad));
            }
        }
#pragma unroll
        for (int mi = 0; mi < 2; mi++)
#pragma unroll
            for (int ni = 0; ni < 4; ni++)
                asm volatile("mma.sync.aligned.m16n8k16.row.col.f32.f16.f16.f32 "
                             "{%0,%1,%2,%3}, {%4,%5,%6,%7}, {%8,%9}, {%0,%1,%2,%3};"
                             : "+f"(acc[mi][ni][0]), "+f"(acc[mi][ni][1]),
                               "+f"(acc[mi][ni][2]), "+f"(acc[mi][ni][3])
                             : "r"(a[mi][0]), "r"(a[mi][1]), "r"(a[mi][2]), "r"(a[mi][3]),
                               "r"(bf[ni][0]), "r"(bf[ni][1]));
    }

    // ---- epilogue ----
    const int g   = lane >> 2;
    const int tig = lane & 3;
    if (ct < 4) {
        const int h = ct;
#pragma unroll
        for (int mi = 0; mi < 2; mi++) {
            const int lr1 = wr + mi * 16 + g;
            const int lr2 = lr1 + 8;
            float sS1 = 0.f, sT1 = 0.f, sS2 = 0.f, sT2 = 0.f;
#pragma unroll
            for (int ni = 0; ni < 4; ni++) {
                const int c0c = wc + ni * 8 + tig * 2;
                const float sv0 = score_src[h * FOUT + c0c];
                const float sv1 = score_src[h * FOUT + c0c + 1];
                const float tv0 = score_tgt[h * FOUT + c0c];
                const float tv1 = score_tgt[h * FOUT + c0c + 1];
                const float2 hi = {acc[mi][ni][0], acc[mi][ni][1]};
                const float2 lo = {acc[mi][ni][2], acc[mi][ni][3]};
                *(unsigned*)((char*)g_h2 + (((size_t)h * N_NODES + r0 + lr1) * FOUT + c0c) * 2) = pack_half2(hi.x, hi.y);
                *(unsigned*)((char*)g_h2 + (((size_t)h * N_NODES + r0 + lr2) * FOUT + c0c) * 2) = pack_half2(lo.x, lo.y);
                sS1 += hi.x * sv0 + hi.y * sv1;  sT1 += hi.x * tv0 + hi.y * tv1;
                sS2 += lo.x * sv0 + lo.y * sv1;  sT2 += lo.x * tv0 + lo.y * tv1;
            }
#pragma unroll
            for (int o = 1; o < 4; o <<= 1) {
                sS1 += __shfl_xor_sync(0xffffffffu, sS1, o);
                sT1 += __shfl_xor_sync(0xffffffffu, sT1, o);
                sS2 += __shfl_xor_sync(0xffffffffu, sS2, o);
                sT2 += __shfl_xor_sync(0xffffffffu, sT2, o);
            }
            if (tig == 0) {
                redS[w & 1][lr1] = sS1;  redT[w & 1][lr1] = sT1;
                redS[w & 1][lr2] = sS2;  redT[w & 1][lr2] = sT2;
            }
        }
        __syncthreads();
        if (tid < 64) {
            g_ss[(r0 + tid) * NH + h] = redS[0][tid] + redS[1][tid];
            g_st[(r0 + tid) * NH + h] = redT[0][tid] + redT[1][tid];
        }
    } else {
        const int c0g = (ct - 4) * 64;
#pragma unroll
        for (int mi = 0; mi < 2; mi++) {
            const int lr1 = wr + mi * 16 + g;
            const int lr2 = lr1 + 8;
#pragma unroll
            for (int ni = 0; ni < 4; ni++) {
                const int cc = c0g + wc + ni * 8 + tig * 2;
                const float2 hi = {acc[mi][ni][0], acc[mi][ni][1]};
                const float2 lo = {acc[mi][ni][2], acc[mi][ni][3]};
                *(float2*)(g_skip + (size_t)(r0 + lr1) * HF + cc) = hi;
                *(float2*)(g_skip + (size_t)(r0 + lr2) * HF + cc) = lo;
            }
        }
    }
}

// ============================================================
// Attention kernel: fp16 gathers; products in fp16 (HMUL2/HFMA2
// chains of <=4 terms, e pre-scaled by 1/4096 to avoid overflow),
// flushed to packed-fp32 accumulators per 4-neighbor batch.
// ============================================================
__global__ __launch_bounds__(128) void attn_kernel(
    const float* __restrict__ bias,
    float* __restrict__ out)
{
    const int n    = blockIdx.x;
    const int tid  = threadIdx.x;
    const int h    = tid >> 5;
    const int lane = tid & 31;

    __shared__ uint2 pair[NH][MAXD];     // {half2(e*c, e*c), byte offset} — 8 KB
    __shared__ float partS[NH][NH + 1];

    const int deg = g_deg[n];
    const float4 ss4 = *(const float4*)(g_ss + (size_t)n * NH);
    const float4* st4 = (const float4*)g_st;
    const unsigned short* adj = g_adj + (size_t)n * MAXD;

    float s0 = 0.f, s1 = 0.f, s2 = 0.f, s3 = 0.f;
    for (int j = tid; j < deg; j += 128) {
        const int m = adj[j];
        const float4 st = st4[m];
        float v0 = ss4.x + st.x; v0 = v0 > 0.f ? v0 : 0.2f * v0;
        float v1 = ss4.y + st.y; v1 = v1 > 0.f ? v1 : 0.2f * v1;
        float v2 = ss4.z + st.z; v2 = v2 > 0.f ? v2 : 0.2f * v2;
        float v3 = ss4.w + st.w; v3 = v3 > 0.f ? v3 : 0.2f * v3;
        const float e0 = __expf(v0), e1 = __expf(v1);
        const float e2 = __expf(v2), e3 = __expf(v3);
        const unsigned off = (unsigned)(m * (FOUT * 2));   // byte offset of fp16 row
        pair[0][j] = make_uint2(pack_half2(e0 * ESCALE, e0 * ESCALE), off);
        pair[1][j] = make_uint2(pack_half2(e1 * ESCALE, e1 * ESCALE), off);
        pair[2][j] = make_uint2(pack_half2(e2 * ESCALE, e2 * ESCALE), off);
        pair[3][j] = make_uint2(pack_half2(e3 * ESCALE, e3 * ESCALE), off);
        s0 += e0; s1 += e1; s2 += e2; s3 += e3;
    }
#pragma unroll
    for (int o = 16; o; o >>= 1) {
        s0 += __shfl_xor_sync(0xffffffffu, s0, o);
        s1 += __shfl_xor_sync(0xffffffffu, s1, o);
        s2 += __shfl_xor_sync(0xffffffffu, s2, o);
        s3 += __shfl_xor_sync(0xffffffffu, s3, o);
    }
    if (lane == 0) {
        partS[h][0] = s0; partS[h][1] = s1;
        partS[h][2] = s2; partS[h][3] = s3;
    }
    __syncthreads();
    const float S = partS[0][h] + partS[1][h] + partS[2][h] + partS[3][h];

    // gather: subgroup g of 16 lanes handles j = g, g+2, ...; lane q -> 8 bytes (4 halves)
    const int g = lane >> 4;
    const int q = lane & 15;
    const char* hb = (const char*)g_h2 + (size_t)h * N_NODES * (FOUT * 2) + q * 8;
    unsigned long long accLo = 0, accHi = 0;   // packed {f32,f32}
    int j = g;
    for (; j + 6 < deg; j += 8) {
        const uint2 P0 = pair[h][j];
        const uint2 P1 = pair[h][j + 2];
        const uint2 P2 = pair[h][j + 4];
        const uint2 P3 = pair[h][j + 6];
        const uint2 H0 = *(const uint2*)(hb + P0.y);
        const uint2 H1 = *(const uint2*)(hb + P1.y);
        const uint2 H2 = *(const uint2*)(hb + P2.y);
        const uint2 H3 = *(const uint2*)(hb + P3.y);
        __half2 c0 = __hmul2(u2h(P0.x), u2h(H0.x));
        __half2 c1 = __hmul2(u2h(P0.x), u2h(H0.y));
        c0 = __hfma2(u2h(P1.x), u2h(H1.x), c0);
        c1 = __hfma2(u2h(P1.x), u2h(H1.y), c1);
        c0 = __hfma2(u2h(P2.x), u2h(H2.x), c0);
        c1 = __hfma2(u2h(P2.x), u2h(H2.y), c1);
        c0 = __hfma2(u2h(P3.x), u2h(H3.x), c0);
        c1 = __hfma2(u2h(P3.x), u2h(H3.y), c1);
        F2U f0; f0.f = __half22float2(c0);
        F2U f1; f1.f = __half22float2(c1);
        add_f32x2(accLo, f0.u);
        add_f32x2(accHi, f1.u);
    }
    for (; j < deg; j += 2) {
        const uint2 P = pair[h][j];
        const uint2 H = *(const uint2*)(hb + P.y);
        const __half2 c0 = __hmul2(u2h(P.x), u2h(H.x));
        const __half2 c1 = __hmul2(u2h(P.x), u2h(H.y));
        F2U f0; f0.f = __half22float2(c0);
        F2U f1; f1.f = __half22float2(c1);
        add_f32x2(accLo, f0.u);
        add_f32x2(accHi, f1.u);
    }
    F2U rLo; rLo.u = accLo;
    F2U rHi; rHi.u = accHi;
    float4 a = {rLo.f.x, rLo.f.y, rHi.f.x, rHi.f.y};
    a.x += __shfl_xor_sync(0xffffffffu, a.x, 16);
    a.y += __shfl_xor_sync(0xffffffffu, a.y, 16);
    a.z += __shfl_xor_sync(0xffffffffu, a.z, 16);
    a.w += __shfl_xor_sync(0xffffffffu, a.w, 16);

    if (g == 0) {
        const float inv = (1.0f / ESCALE) / S;   // undo e-scaling + normalize
        const int c4 = h * 16 + q;
        const float4 sk = ((const float4*)(g_skip + (size_t)n * HF))[c4];
        const float4 bi = ((const float4*)bias)[c4];
        float o0 = a.x * inv + sk.x + bi.x;
        float o1 = a.y * inv + sk.y + bi.y;
        float o2 = a.z * inv + sk.z + bi.z;
        float o3 = a.w * inv + sk.w + bi.w;
        o0 = o0 > 0.f ? o0 : (__expf(o0) - 1.f);
        o1 = o1 > 0.f ? o1 : (__expf(o1) - 1.f);
        o2 = o2 > 0.f ? o2 : (__expf(o2) - 1.f);
        o3 = o3 > 0.f ? o3 : (__expf(o3) - 1.f);
        const float4 res = {o0, o1, o2, o3};
        ((float4*)(out + (size_t)n * HF))[c4] = res;
    }
}

// ============================================================
extern "C" void kernel_launch(void* const* d_in, const int* in_sizes, int n_in,
                              void* d_out, int out_size)
{
    const float* x         = (const float*)d_in[0];
    const float* mask      = (const float*)d_in[1];
    const float* proj      = (const float*)d_in[2];
    const float* score_src = (const float*)d_in[3];
    const float* score_tgt = (const float*)d_in[4];
    const float* skip_w    = (const float*)d_in[5];
    const float* bias      = (const float*)d_in[6];
    float* out             = (float*)d_out;

    prep_kernel<<<NBLK, 128>>>(x, mask, proj, score_src, score_tgt, skip_w);
    attn_kernel<<<N_NODES, 128>>>(bias, out);
}